// round 1
// baseline (speedup 1.0000x reference)
#include <cuda_runtime.h>
#include <math.h>
#include <stdint.h>

#define B_  4
#define T_  2048
#define E_  1024
#define H_  16
#define DH_ 64
#define NL_ 4
#define FF_ 4096
#define V_  32000
#define BT_ (B_*T_)        // 8192 tokens
#define MQKV_ (BT_*H_)     // 131072 per-head rows

// ---------------- scratch (static device allocations; no cudaMalloc) -------
__device__ float g_x[BT_*E_];
__device__ float g_y[BT_*E_];
__device__ float g_q[BT_*E_];
__device__ float g_k[BT_*E_];
__device__ float g_v[BT_*E_];
__device__ float g_att[BT_*E_];
__device__ float g_h[(size_t)BT_*FF_];
__device__ float g_logits[(size_t)BT_*V_];   // used only if d_out can't hold logits
__device__ float g_tokloss[BT_];

// ---------------- generic SGEMM: C[M,N] = A[M,K] @ W[N,K]^T (+epilogue) ----
#define EPI_BIAS 1
#define EPI_RES  2
#define EPI_GELU 4

template<int EPI>
__global__ void __launch_bounds__(256) gemm_kernel(
    const float* __restrict__ A, const float* __restrict__ W,
    const float* __restrict__ bias, const float* __restrict__ res,
    float* __restrict__ C, int M, int N, int K)
{
    __shared__ float As[16][132];
    __shared__ float Bs[16][132];
    const int tid = threadIdx.x;
    const int m0 = blockIdx.y * 128;
    const int n0 = blockIdx.x * 128;
    const int tx = tid & 15, ty = tid >> 4;
    const int lr = tid >> 2;            // 0..63
    const int lc = (tid & 3) << 2;      // 0,4,8,12

    float acc[8][8];
    #pragma unroll
    for (int i = 0; i < 8; i++)
        #pragma unroll
        for (int j = 0; j < 8; j++) acc[i][j] = 0.f;

    for (int k0 = 0; k0 < K; k0 += 16) {
        #pragma unroll
        for (int p = 0; p < 2; p++) {
            int row = lr + p * 64;
            int gm = m0 + row;
            float4 va = make_float4(0.f, 0.f, 0.f, 0.f);
            if (gm < M) va = *(const float4*)(A + (size_t)gm * K + k0 + lc);
            As[lc+0][row] = va.x; As[lc+1][row] = va.y;
            As[lc+2][row] = va.z; As[lc+3][row] = va.w;
            int gn = n0 + row;
            float4 vb = make_float4(0.f, 0.f, 0.f, 0.f);
            if (gn < N) vb = *(const float4*)(W + (size_t)gn * K + k0 + lc);
            Bs[lc+0][row] = vb.x; Bs[lc+1][row] = vb.y;
            Bs[lc+2][row] = vb.z; Bs[lc+3][row] = vb.w;
        }
        __syncthreads();
        #pragma unroll
        for (int kk = 0; kk < 16; kk++) {
            float a[8], b[8];
            #pragma unroll
            for (int i = 0; i < 8; i++) a[i] = As[kk][ty*8+i];
            #pragma unroll
            for (int j = 0; j < 8; j++) b[j] = Bs[kk][tx*8+j];
            #pragma unroll
            for (int i = 0; i < 8; i++)
                #pragma unroll
                for (int j = 0; j < 8; j++)
                    acc[i][j] = fmaf(a[i], b[j], acc[i][j]);
        }
        __syncthreads();
    }

    #pragma unroll
    for (int i = 0; i < 8; i++) {
        int gm = m0 + ty*8 + i;
        if (gm >= M) continue;
        #pragma unroll
        for (int j = 0; j < 8; j++) {
            int gn = n0 + tx*8 + j;
            if (gn >= N) continue;
            float vv = acc[i][j];
            if (EPI & EPI_BIAS) vv += bias[gn];
            if (EPI & EPI_RES)  vv += res[(size_t)gm * N + gn];
            if (EPI & EPI_GELU) vv = 0.5f * vv * (1.f + erff(vv * 0.70710678118654752f));
            C[(size_t)gm * N + gn] = vv;
        }
    }
}

// ---------------- flash attention (causal, online softmax) -----------------
// grid: (T/64, B*H). block: 256 threads = 16x16, each thread 4x4 microtile.
#define ATTN_SMEM_FLOATS (4*64*65 + 3*64)
#define ATTN_SMEM_BYTES  (ATTN_SMEM_FLOATS * 4)

__global__ void __launch_bounds__(256) attn_kernel(
    const float* __restrict__ q, const float* __restrict__ k,
    const float* __restrict__ v, float* __restrict__ out)
{
    extern __shared__ float sm[];
    float* Qs  = sm;
    float* Ks  = sm + 64*65;
    float* Vs  = sm + 2*64*65;
    float* Ps  = sm + 3*64*65;
    float* m_s = sm + 4*64*65;
    float* l_s = m_s + 64;
    float* al_s= l_s + 64;

    const int qt = blockIdx.x;
    const int bh = blockIdx.y;
    const int b  = bh / H_, h = bh % H_;
    const int q0 = qt * 64;
    const int tid = threadIdx.x;
    const int tx = tid & 15, ty = tid >> 4;

    // Load Q tile [64 x 64]
    {
        int r  = tid >> 2;
        int c0 = (tid & 3) * 16;
        const float* src = q + ((size_t)(b * T_ + q0 + r) * H_ + h) * DH_ + c0;
        #pragma unroll
        for (int j = 0; j < 4; j++) {
            float4 t4 = *(const float4*)(src + j*4);
            Qs[r*65 + c0 + j*4 + 0] = t4.x;
            Qs[r*65 + c0 + j*4 + 1] = t4.y;
            Qs[r*65 + c0 + j*4 + 2] = t4.z;
            Qs[r*65 + c0 + j*4 + 3] = t4.w;
        }
    }
    if (tid < 64) { m_s[tid] = -1e30f; l_s[tid] = 0.f; }

    float o[4][4];
    #pragma unroll
    for (int i = 0; i < 4; i++)
        #pragma unroll
        for (int j = 0; j < 4; j++) o[i][j] = 0.f;

    for (int kt = 0; kt <= qt; kt++) {
        const int k0 = kt * 64;
        __syncthreads();   // prior-iter Ps/Vs consumers done; also fences Q/stats init
        {
            int r  = tid >> 2;
            int c0 = (tid & 3) * 16;
            const float* ks = k + ((size_t)(b * T_ + k0 + r) * H_ + h) * DH_ + c0;
            const float* vs = v + ((size_t)(b * T_ + k0 + r) * H_ + h) * DH_ + c0;
            #pragma unroll
            for (int j = 0; j < 4; j++) {
                float4 t4 = *(const float4*)(ks + j*4);
                Ks[r*65+c0+j*4+0] = t4.x; Ks[r*65+c0+j*4+1] = t4.y;
                Ks[r*65+c0+j*4+2] = t4.z; Ks[r*65+c0+j*4+3] = t4.w;
                float4 u4 = *(const float4*)(vs + j*4);
                Vs[r*65+c0+j*4+0] = u4.x; Vs[r*65+c0+j*4+1] = u4.y;
                Vs[r*65+c0+j*4+2] = u4.z; Vs[r*65+c0+j*4+3] = u4.w;
            }
        }
        __syncthreads();

        // S = Q K^T (4x4 microtile per thread)
        float s[4][4];
        #pragma unroll
        for (int i = 0; i < 4; i++)
            #pragma unroll
            for (int j = 0; j < 4; j++) s[i][j] = 0.f;
        for (int d = 0; d < 64; d++) {
            float a[4], bb[4];
            #pragma unroll
            for (int i = 0; i < 4; i++) a[i]  = Qs[(ty*4+i)*65 + d];
            #pragma unroll
            for (int j = 0; j < 4; j++) bb[j] = Ks[(tx*4+j)*65 + d];
            #pragma unroll
            for (int i = 0; i < 4; i++)
                #pragma unroll
                for (int j = 0; j < 4; j++)
                    s[i][j] = fmaf(a[i], bb[j], s[i][j]);
        }
        const bool diag = (kt == qt);
        #pragma unroll
        for (int i = 0; i < 4; i++)
            #pragma unroll
            for (int j = 0; j < 4; j++) {
                float val = s[i][j] * 0.125f;   // 1/sqrt(64)
                if (diag && (tx*4+j) > (ty*4+i)) val = -1e30f;
                Ps[(ty*4+i)*65 + tx*4+j] = val;
            }
        __syncthreads();

        // Online softmax: 4 lanes per row (aligned groups within a warp)
        {
            int r  = tid >> 2;
            int c0 = (tid & 3) * 16;
            float mx = -1e30f;
            for (int c = 0; c < 16; c++) mx = fmaxf(mx, Ps[r*65 + c0 + c]);
            mx = fmaxf(mx, __shfl_xor_sync(0xffffffffu, mx, 1));
            mx = fmaxf(mx, __shfl_xor_sync(0xffffffffu, mx, 2));
            float m_old = m_s[r];
            float m_new = fmaxf(m_old, mx);
            float ssum = 0.f;
            for (int c = 0; c < 16; c++) {
                float p = __expf(Ps[r*65 + c0 + c] - m_new);
                Ps[r*65 + c0 + c] = p;
                ssum += p;
            }
            ssum += __shfl_xor_sync(0xffffffffu, ssum, 1);
            ssum += __shfl_xor_sync(0xffffffffu, ssum, 2);
            if ((tid & 3) == 0) {
                float alpha = __expf(m_old - m_new);
                al_s[r] = alpha;
                m_s[r]  = m_new;
                l_s[r]  = l_s[r] * alpha + ssum;
            }
        }
        __syncthreads();

        // Rescale O and accumulate P @ V
        float al[4];
        #pragma unroll
        for (int i = 0; i < 4; i++) al[i] = al_s[ty*4+i];
        #pragma unroll
        for (int i = 0; i < 4; i++)
            #pragma unroll
            for (int j = 0; j < 4; j++) o[i][j] *= al[i];
        for (int c = 0; c < 64; c++) {
            float p[4], vv[4];
            #pragma unroll
            for (int i = 0; i < 4; i++) p[i]  = Ps[(ty*4+i)*65 + c];
            #pragma unroll
            for (int j = 0; j < 4; j++) vv[j] = Vs[c*65 + tx*4+j];
            #pragma unroll
            for (int i = 0; i < 4; i++)
                #pragma unroll
                for (int j = 0; j < 4; j++)
                    o[i][j] = fmaf(p[i], vv[j], o[i][j]);
        }
    }

    #pragma unroll
    for (int i = 0; i < 4; i++) {
        int r = ty*4 + i;
        float inv = 1.0f / l_s[r];
        float* dst = out + ((size_t)(b * T_ + q0 + r) * H_ + h) * DH_ + tx*4;
        #pragma unroll
        for (int j = 0; j < 4; j++) dst[j] = o[i][j] * inv;
    }
}

// ---------------- layernorm (one block per row of E=1024) ------------------
__global__ void __launch_bounds__(256) ln_kernel(
    const float* __restrict__ in, const float* __restrict__ gg,
    const float* __restrict__ bb, float* __restrict__ out)
{
    __shared__ float red[8];
    const int row = blockIdx.x;
    const int tid = threadIdx.x;
    float4 vx = ((const float4*)(in + (size_t)row * E_))[tid];
    float s = vx.x + vx.y + vx.z + vx.w;
    #pragma unroll
    for (int o = 16; o; o >>= 1) s += __shfl_xor_sync(0xffffffffu, s, o);
    if ((tid & 31) == 0) red[tid >> 5] = s;
    __syncthreads();
    float mean = (red[0]+red[1]+red[2]+red[3]+red[4]+red[5]+red[6]+red[7]) * (1.f/E_);
    __syncthreads();
    float dx = vx.x - mean, dy = vx.y - mean, dz = vx.z - mean, dw = vx.w - mean;
    float s2 = dx*dx + dy*dy + dz*dz + dw*dw;
    #pragma unroll
    for (int o = 16; o; o >>= 1) s2 += __shfl_xor_sync(0xffffffffu, s2, o);
    if ((tid & 31) == 0) red[tid >> 5] = s2;
    __syncthreads();
    float var = (red[0]+red[1]+red[2]+red[3]+red[4]+red[5]+red[6]+red[7]) * (1.f/E_);
    float rstd = rsqrtf(var + 1e-5f);
    float4 g4 = ((const float4*)gg)[tid];
    float4 b4 = ((const float4*)bb)[tid];
    float4 o4 = make_float4(dx*rstd*g4.x + b4.x, dy*rstd*g4.y + b4.y,
                            dz*rstd*g4.z + b4.z, dw*rstd*g4.w + b4.w);
    ((float4*)(out + (size_t)row * E_))[tid] = o4;
}

// ---------------- token+pos embedding --------------------------------------
__global__ void __launch_bounds__(256) embed_kernel(
    const int* __restrict__ idx, const float* __restrict__ tok,
    const float* __restrict__ pos, float* __restrict__ out)
{
    int gid = blockIdx.x * 256 + threadIdx.x;    // over BT*E/4
    int e4 = gid & (E_/4 - 1);
    int bt = gid >> 8;                            // /(E/4)
    int t  = bt & (T_ - 1);
    int token = idx[bt];
    float4 a = ((const float4*)(tok + (size_t)token * E_))[e4];
    float4 p = ((const float4*)(pos + (size_t)t * E_))[e4];
    ((float4*)out)[gid] = make_float4(a.x+p.x, a.y+p.y, a.z+p.z, a.w+p.w);
}

// ---------------- loss: per-token log-softmax then deterministic reduce ----
__global__ void __launch_bounds__(256) loss_tok_kernel(
    const float* __restrict__ logits, const int* __restrict__ targets,
    float* __restrict__ tokloss)
{
    __shared__ float red[8];
    const int row = blockIdx.x;
    const int tid = threadIdx.x;
    const float* lg = logits + (size_t)row * V_;
    float mx = -1e30f;
    for (int i = tid; i < V_; i += 256) mx = fmaxf(mx, lg[i]);
    #pragma unroll
    for (int o = 16; o; o >>= 1) mx = fmaxf(mx, __shfl_xor_sync(0xffffffffu, mx, o));
    if ((tid & 31) == 0) red[tid >> 5] = mx;
    __syncthreads();
    mx = fmaxf(fmaxf(fmaxf(red[0], red[1]), fmaxf(red[2], red[3])),
               fmaxf(fmaxf(red[4], red[5]), fmaxf(red[6], red[7])));
    __syncthreads();
    float s = 0.f;
    for (int i = tid; i < V_; i += 256) s += __expf(lg[i] - mx);
    #pragma unroll
    for (int o = 16; o; o >>= 1) s += __shfl_xor_sync(0xffffffffu, s, o);
    if ((tid & 31) == 0) red[tid >> 5] = s;
    __syncthreads();
    if (tid == 0) {
        float tot = red[0]+red[1]+red[2]+red[3]+red[4]+red[5]+red[6]+red[7];
        tokloss[row] = -(lg[targets[row]] - mx - logf(tot));
    }
}

__global__ void __launch_bounds__(256) loss_reduce_kernel(
    const float* __restrict__ tokloss, float* __restrict__ outp)
{
    __shared__ float red[8];
    const int tid = threadIdx.x;
    float s = 0.f;
    for (int i = tid; i < BT_; i += 256) s += tokloss[i];
    #pragma unroll
    for (int o = 16; o; o >>= 1) s += __shfl_xor_sync(0xffffffffu, s, o);
    if ((tid & 31) == 0) red[tid >> 5] = s;
    __syncthreads();
    if (tid == 0) {
        float tot = red[0]+red[1]+red[2]+red[3]+red[4]+red[5]+red[6]+red[7];
        outp[0] = tot / (float)BT_;
    }
}

// ---------------- host driver ----------------------------------------------
extern "C" void kernel_launch(void* const* d_in, const int* in_sizes, int n_in,
                              void* d_out, int out_size)
{
    const int*   idx  = (const int*)  d_in[0];
    const int*   tgt  = (const int*)  d_in[1];
    const float* tok  = (const float*)d_in[2];
    const float* pos  = (const float*)d_in[3];
    const float* Wq   = (const float*)d_in[4];
    const float* Wk   = (const float*)d_in[5];
    const float* Wv   = (const float*)d_in[6];
    const float* Wo   = (const float*)d_in[7];
    const float* bo   = (const float*)d_in[8];
    const float* ln1g = (const float*)d_in[9];
    const float* ln1b = (const float*)d_in[10];
    const float* W1   = (const float*)d_in[11];
    const float* b1   = (const float*)d_in[12];
    const float* W2   = (const float*)d_in[13];
    const float* b2   = (const float*)d_in[14];
    const float* ln2g = (const float*)d_in[15];
    const float* ln2b = (const float*)d_in[16];
    const float* lnfg = (const float*)d_in[17];
    const float* lnfb = (const float*)d_in[18];
    const float* lmw  = (const float*)d_in[19];
    const float* lmb  = (const float*)d_in[20];

    float *x, *y, *q, *k, *v, *att, *hbuf, *lscratch, *tokloss;
    cudaGetSymbolAddress((void**)&x,        g_x);
    cudaGetSymbolAddress((void**)&y,        g_y);
    cudaGetSymbolAddress((void**)&q,        g_q);
    cudaGetSymbolAddress((void**)&k,        g_k);
    cudaGetSymbolAddress((void**)&v,        g_v);
    cudaGetSymbolAddress((void**)&att,      g_att);
    cudaGetSymbolAddress((void**)&hbuf,     g_h);
    cudaGetSymbolAddress((void**)&lscratch, g_logits);
    cudaGetSymbolAddress((void**)&tokloss,  g_tokloss);

    const size_t LOG_N = (size_t)BT_ * V_;
    float* logits_ptr = ((size_t)out_size >= LOG_N) ? (float*)d_out : lscratch;
    float* loss_ptr = nullptr;
    if ((size_t)out_size >= LOG_N + 1) loss_ptr = (float*)d_out + LOG_N;
    else if ((size_t)out_size < LOG_N) loss_ptr = (float*)d_out;

    cudaFuncSetAttribute(attn_kernel, cudaFuncAttributeMaxDynamicSharedMemorySize,
                         ATTN_SMEM_BYTES);

    embed_kernel<<<BT_*(E_/4)/256, 256>>>(idx, tok, pos, x);

    for (int l = 0; l < NL_; l++) {
        gemm_kernel<0><<<dim3(1, MQKV_/128), 256>>>(
            x, Wq + (size_t)l*DH_*DH_, nullptr, nullptr, q, MQKV_, DH_, DH_);
        gemm_kernel<0><<<dim3(1, MQKV_/128), 256>>>(
            x, Wk + (size_t)l*DH_*DH_, nullptr, nullptr, k, MQKV_, DH_, DH_);
        gemm_kernel<0><<<dim3(1, MQKV_/128), 256>>>(
            x, Wv + (size_t)l*DH_*DH_, nullptr, nullptr, v, MQKV_, DH_, DH_);

        attn_kernel<<<dim3(T_/64, B_*H_), 256, ATTN_SMEM_BYTES>>>(q, k, v, att);

        gemm_kernel<EPI_BIAS|EPI_RES><<<dim3(E_/128, BT_/128), 256>>>(
            att, Wo + (size_t)l*E_*E_, bo + (size_t)l*E_, x, y, BT_, E_, E_);
        ln_kernel<<<BT_, 256>>>(y, ln1g + (size_t)l*E_, ln1b + (size_t)l*E_, x);

        gemm_kernel<EPI_BIAS|EPI_GELU><<<dim3(FF_/128, BT_/128), 256>>>(
            x, W1 + (size_t)l*FF_*E_, b1 + (size_t)l*FF_, nullptr, hbuf, BT_, FF_, E_);
        gemm_kernel<EPI_BIAS|EPI_RES><<<dim3(E_/128, BT_/128), 256>>>(
            hbuf, W2 + (size_t)l*E_*FF_, b2 + (size_t)l*E_, x, y, BT_, E_, FF_);
        ln_kernel<<<BT_, 256>>>(y, ln2g + (size_t)l*E_, ln2b + (size_t)l*E_, x);
    }

    ln_kernel<<<BT_, 256>>>(x, lnfg, lnfb, y);

    gemm_kernel<EPI_BIAS><<<dim3(V_/128, BT_/128), 256>>>(
        y, lmw, lmb, nullptr, logits_ptr, BT_, V_, E_);

    if (loss_ptr) {
        loss_tok_kernel<<<BT_, 256>>>(logits_ptr, tgt, tokloss);
        loss_reduce_kernel<<<1, 256>>>(tokloss, loss_ptr);
    }
}

// round 8
// speedup vs baseline: 1.1702x; 1.1702x over previous
#include <cuda_runtime.h>
#include <cuda_bf16.h>
#include <math.h>
#include <stdint.h>

#define B_  4
#define T_  2048
#define E_  1024
#define H_  16
#define DH_ 64
#define NL_ 4
#define FF_ 4096
#define V_  32000
#define BT_ (B_*T_)        // 8192 tokens
#define MQKV_ (BT_*H_)     // 131072 per-head rows

// ---------------- scratch (static device allocations; no cudaMalloc) -------
__device__ float g_x[BT_*E_];
__device__ float g_y[BT_*E_];
__device__ float g_q[BT_*E_];
__device__ float g_k[BT_*E_];
__device__ float g_v[BT_*E_];
__device__ float g_att[BT_*E_];
__device__ float g_h[(size_t)BT_*FF_];
__device__ float g_logits[(size_t)BT_*V_];
__device__ float g_tokloss[BT_];
// bf16 hi/lo split buffers
__device__ __nv_bfloat16 g_ah[(size_t)BT_*FF_];
__device__ __nv_bfloat16 g_al[(size_t)BT_*FF_];
__device__ __nv_bfloat16 g_wh[(size_t)V_*E_];
__device__ __nv_bfloat16 g_wl[(size_t)V_*E_];

// ======================= low-level helpers =================================
__device__ __forceinline__ uint32_t smem_u32(const void* p) {
    uint32_t a;
    asm("{ .reg .u64 t; cvta.to.shared.u64 t, %1; cvt.u32.u64 %0, t; }"
        : "=r"(a) : "l"(p));
    return a;
}
__device__ __forceinline__ void cp16(uint32_t dst, const void* src) {
    asm volatile("cp.async.cg.shared.global [%0], [%1], 16;\n"
                 :: "r"(dst), "l"(src));
}
__device__ __forceinline__ void cp_commit() {
    asm volatile("cp.async.commit_group;" ::: "memory");
}
__device__ __forceinline__ void cp_wait1() {
    asm volatile("cp.async.wait_group 1;" ::: "memory");
}
__device__ __forceinline__ void cp_wait0() {
    asm volatile("cp.async.wait_group 0;" ::: "memory");
}
#define LDSM4(r0,r1,r2,r3,addr) \
    asm volatile("ldmatrix.sync.aligned.m8n8.x4.shared.b16 {%0,%1,%2,%3}, [%4];" \
        : "=r"(r0),"=r"(r1),"=r"(r2),"=r"(r3) : "r"(addr))
#define LDSM2(r0,r1,addr) \
    asm volatile("ldmatrix.sync.aligned.m8n8.x2.shared.b16 {%0,%1}, [%2];" \
        : "=r"(r0),"=r"(r1) : "r"(addr))
#define MMA16816(c,a,b) \
    asm volatile("mma.sync.aligned.m16n8k16.row.col.f32.bf16.bf16.f32 " \
        "{%0,%1,%2,%3}, {%4,%5,%6,%7}, {%8,%9}, {%0,%1,%2,%3};" \
        : "+f"((c)[0]),"+f"((c)[1]),"+f"((c)[2]),"+f"((c)[3]) \
        : "r"((a)[0]),"r"((a)[1]),"r"((a)[2]),"r"((a)[3]), \
          "r"((b)[0]),"r"((b)[1]))

// ======================= bf16 hi/lo HMMA GEMM ==============================
// C[M,N] = (Ah+Al)[M,K] @ (Bh+Bl)[N,K]^T, fp32 out, 3-pass split precision.
// Block 128x128, K-chunk 32, 8 warps (2M x 4N, warp tile 64x32), 2-stage
// cp.async pipeline, 80B-padded smem rows (conflict-free ldmatrix).
#define EPI_BIAS 1
#define EPI_RES  2
#define EPI_GELU 4

#define PAD_ROW 80                    // bytes per smem row: 64B data + 16B pad
#define TILE_BYTES (128*PAD_ROW)      // 10240
#define S_AH 0
#define S_AL (TILE_BYTES)
#define S_BH (2*TILE_BYTES)
#define S_BL (3*TILE_BYTES)
#define STAGE_MM (4*TILE_BYTES)       // 40960
#define SMEM_MM  (2*STAGE_MM)         // 81920

__device__ __forceinline__ void mm_load(
    uint32_t st, const __nv_bfloat16* __restrict__ Ah,
    const __nv_bfloat16* __restrict__ Al,
    const __nv_bfloat16* __restrict__ Bh,
    const __nv_bfloat16* __restrict__ Bl,
    int m0, int n0, int K, int k0, int tid)
{
    #pragma unroll
    for (int j = 0; j < 2; j++) {
        int ch  = tid + j * 256;          // 0..511
        int row = ch >> 2;
        int c16 = ch & 3;
        uint32_t so = row * PAD_ROW + c16 * 16;
        size_t goA = (size_t)(m0 + row) * K + k0 + c16 * 8;
        size_t goB = (size_t)(n0 + row) * K + k0 + c16 * 8;
        cp16(st + S_AH + so, Ah + goA);
        cp16(st + S_AL + so, Al + goA);
        cp16(st + S_BH + so, Bh + goB);
        cp16(st + S_BL + so, Bl + goB);
    }
}

template<int EPI>
__global__ void __launch_bounds__(256) gemm_mm(
    const __nv_bfloat16* __restrict__ Ah, const __nv_bfloat16* __restrict__ Al,
    const __nv_bfloat16* __restrict__ Bh, const __nv_bfloat16* __restrict__ Bl,
    const float* __restrict__ bias, const float* __restrict__ res,
    float* __restrict__ C, int M, int N, int K)
{
    extern __shared__ char smraw[];
    const uint32_t sb = smem_u32(smraw);
    const int tid  = threadIdx.x;
    const int lane = tid & 31;
    const int wid  = tid >> 5;
    const int wm = (wid & 1) * 64;        // warp M offset in block
    const int wn = (wid >> 1) * 32;       // warp N offset in block
    const int m0 = blockIdx.x * 128;
    const int n0 = blockIdx.y * 128;
    const int NC = K >> 5;                // chunks of 32

    float c[4][4][4];
    #pragma unroll
    for (int i = 0; i < 4; i++)
        #pragma unroll
        for (int j = 0; j < 4; j++)
            #pragma unroll
            for (int r = 0; r < 4; r++) c[i][j][r] = 0.f;

    // ldmatrix per-lane address components (constant across chunks)
    const int a_row = wm + (lane & 15);             // row within block A tile
    const int a_kof = (lane >> 4) * 8;              // k offset within 16-step
    const int b_row = wn + (lane & 7);              // base B row (ni adds 8*ni)
    const int b_kof = ((lane >> 3) & 1) * 8;

    mm_load(sb, Ah, Al, Bh, Bl, m0, n0, K, 0, tid);
    cp_commit();

    for (int ck = 0; ck < NC; ck++) {
        if (ck + 1 < NC) {
            mm_load(sb + ((ck + 1) & 1) * STAGE_MM, Ah, Al, Bh, Bl,
                    m0, n0, K, (ck + 1) << 5, tid);
            cp_commit();
            cp_wait1();
        } else {
            cp_wait0();
        }
        __syncthreads();

        const uint32_t st = sb + (ck & 1) * STAGE_MM;
        #pragma unroll
        for (int ks = 0; ks < 2; ks++) {
            const int k0 = ks * 16;
            uint32_t ah[4][4], al[4][4], bh[4][2], bl[4][2];
            #pragma unroll
            for (int mi = 0; mi < 4; mi++) {
                uint32_t ad = st + (a_row + mi * 16) * PAD_ROW + (k0 + a_kof) * 2;
                LDSM4(ah[mi][0], ah[mi][1], ah[mi][2], ah[mi][3], ad + S_AH);
                LDSM4(al[mi][0], al[mi][1], al[mi][2], al[mi][3], ad + S_AL);
            }
            #pragma unroll
            for (int ni = 0; ni < 4; ni++) {
                uint32_t bd = st + (b_row + ni * 8) * PAD_ROW + (k0 + b_kof) * 2;
                LDSM2(bh[ni][0], bh[ni][1], bd + S_BH);
                LDSM2(bl[ni][0], bl[ni][1], bd + S_BL);
            }
            #pragma unroll
            for (int mi = 0; mi < 4; mi++)
                #pragma unroll
                for (int ni = 0; ni < 4; ni++) {
                    MMA16816(c[mi][ni], ah[mi], bh[ni]);
                    MMA16816(c[mi][ni], ah[mi], bl[ni]);
                    MMA16816(c[mi][ni], al[mi], bh[ni]);
                }
        }
        __syncthreads();
    }

    // epilogue: c frag rows = lane>>2 (+8), cols = 2*(lane&3) (+1)
    #pragma unroll
    for (int mi = 0; mi < 4; mi++) {
        const int mr = m0 + wm + mi * 16 + (lane >> 2);
        #pragma unroll
        for (int half = 0; half < 2; half++) {
            const int m = mr + half * 8;
            #pragma unroll
            for (int ni = 0; ni < 4; ni++) {
                const int n = n0 + wn + ni * 8 + 2 * (lane & 3);
                float v0 = c[mi][ni][half * 2 + 0];
                float v1 = c[mi][ni][half * 2 + 1];
                if (EPI & EPI_BIAS) { v0 += bias[n]; v1 += bias[n + 1]; }
                if (EPI & EPI_RES) {
                    float2 r2 = *(const float2*)(res + (size_t)m * N + n);
                    v0 += r2.x; v1 += r2.y;
                }
                if (EPI & EPI_GELU) {
                    v0 = 0.5f * v0 * (1.f + erff(v0 * 0.70710678118654752f));
                    v1 = 0.5f * v1 * (1.f + erff(v1 * 0.70710678118654752f));
                }
                *(float2*)(C + (size_t)m * N + n) = make_float2(v0, v1);
            }
        }
    }
}

// ---------------- fp32 -> bf16 hi/lo conversion ----------------------------
__global__ void __launch_bounds__(256) cvt_kernel(
    const float* __restrict__ in, __nv_bfloat16* __restrict__ hi,
    __nv_bfloat16* __restrict__ lo, int n4)
{
    int i = blockIdx.x * 256 + threadIdx.x;
    if (i >= n4) return;
    float4 x = ((const float4*)in)[i];
    __nv_bfloat16 h0 = __float2bfloat16(x.x);
    __nv_bfloat16 h1 = __float2bfloat16(x.y);
    __nv_bfloat16 h2 = __float2bfloat16(x.z);
    __nv_bfloat16 h3 = __float2bfloat16(x.w);
    __nv_bfloat16 l0 = __float2bfloat16(x.x - __bfloat162float(h0));
    __nv_bfloat16 l1 = __float2bfloat16(x.y - __bfloat162float(h1));
    __nv_bfloat16 l2 = __float2bfloat16(x.z - __bfloat162float(h2));
    __nv_bfloat16 l3 = __float2bfloat16(x.w - __bfloat162float(h3));
    ((__nv_bfloat162*)hi)[2*i]   = __nv_bfloat162(h0, h1);
    ((__nv_bfloat162*)hi)[2*i+1] = __nv_bfloat162(h2, h3);
    ((__nv_bfloat162*)lo)[2*i]   = __nv_bfloat162(l0, l1);
    ((__nv_bfloat162*)lo)[2*i+1] = __nv_bfloat162(l2, l3);
}

// ---------------- fp32 SGEMM (kept for tiny QKV: N=K=64) -------------------
template<int EPI>
__global__ void __launch_bounds__(256) gemm_kernel(
    const float* __restrict__ A, const float* __restrict__ W,
    const float* __restrict__ bias, const float* __restrict__ res,
    float* __restrict__ C, int M, int N, int K)
{
    __shared__ float As[16][132];
    __shared__ float Bs[16][132];
    const int tid = threadIdx.x;
    const int m0 = blockIdx.y * 128;
    const int n0 = blockIdx.x * 128;
    const int tx = tid & 15, ty = tid >> 4;
    const int lr = tid >> 2;
    const int lc = (tid & 3) << 2;

    float acc[8][8];
    #pragma unroll
    for (int i = 0; i < 8; i++)
        #pragma unroll
        for (int j = 0; j < 8; j++) acc[i][j] = 0.f;

    for (int k0 = 0; k0 < K; k0 += 16) {
        #pragma unroll
        for (int p = 0; p < 2; p++) {
            int row = lr + p * 64;
            int gm = m0 + row;
            float4 va = make_float4(0.f, 0.f, 0.f, 0.f);
            if (gm < M) va = *(const float4*)(A + (size_t)gm * K + k0 + lc);
            As[lc+0][row] = va.x; As[lc+1][row] = va.y;
            As[lc+2][row] = va.z; As[lc+3][row] = va.w;
            int gn = n0 + row;
            float4 vb = make_float4(0.f, 0.f, 0.f, 0.f);
            if (gn < N) vb = *(const float4*)(W + (size_t)gn * K + k0 + lc);
            Bs[lc+0][row] = vb.x; Bs[lc+1][row] = vb.y;
            Bs[lc+2][row] = vb.z; Bs[lc+3][row] = vb.w;
        }
        __syncthreads();
        #pragma unroll
        for (int kk = 0; kk < 16; kk++) {
            float a[8], b[8];
            #pragma unroll
            for (int i = 0; i < 8; i++) a[i] = As[kk][ty*8+i];
            #pragma unroll
            for (int j = 0; j < 8; j++) b[j] = Bs[kk][tx*8+j];
            #pragma unroll
            for (int i = 0; i < 8; i++)
                #pragma unroll
                for (int j = 0; j < 8; j++)
                    acc[i][j] = fmaf(a[i], b[j], acc[i][j]);
        }
        __syncthreads();
    }

    #pragma unroll
    for (int i = 0; i < 8; i++) {
        int gm = m0 + ty*8 + i;
        if (gm >= M) continue;
        #pragma unroll
        for (int j = 0; j < 8; j++) {
            int gn = n0 + tx*8 + j;
            if (gn >= N) continue;
            float vv = acc[i][j];
            if (EPI & EPI_BIAS) vv += bias[gn];
            if (EPI & EPI_RES)  vv += res[(size_t)gm * N + gn];
            if (EPI & EPI_GELU) vv = 0.5f * vv * (1.f + erff(vv * 0.70710678118654752f));
            C[(size_t)gm * N + gn] = vv;
        }
    }
}

// ---------------- flash attention (causal, online softmax, fp32) -----------
#define ATTN_SMEM_FLOATS (4*64*65 + 3*64)
#define ATTN_SMEM_BYTES  (ATTN_SMEM_FLOATS * 4)

__global__ void __launch_bounds__(256) attn_kernel(
    const float* __restrict__ q, const float* __restrict__ k,
    const float* __restrict__ v, float* __restrict__ out)
{
    extern __shared__ float sm[];
    float* Qs  = sm;
    float* Ks  = sm + 64*65;
    float* Vs  = sm + 2*64*65;
    float* Ps  = sm + 3*64*65;
    float* m_s = sm + 4*64*65;
    float* l_s = m_s + 64;
    float* al_s= l_s + 64;

    const int qt = blockIdx.x;
    const int bh = blockIdx.y;
    const int b  = bh / H_, h = bh % H_;
    const int q0 = qt * 64;
    const int tid = threadIdx.x;
    const int tx = tid & 15, ty = tid >> 4;

    {
        int r  = tid >> 2;
        int c0 = (tid & 3) * 16;
        const float* src = q + ((size_t)(b * T_ + q0 + r) * H_ + h) * DH_ + c0;
        #pragma unroll
        for (int j = 0; j < 4; j++) {
            float4 t4 = *(const float4*)(src + j*4);
            Qs[r*65 + c0 + j*4 + 0] = t4.x;
            Qs[r*65 + c0 + j*4 + 1] = t4.y;
            Qs[r*65 + c0 + j*4 + 2] = t4.z;
            Qs[r*65 + c0 + j*4 + 3] = t4.w;
        }
    }
    if (tid < 64) { m_s[tid] = -1e30f; l_s[tid] = 0.f; }

    float o[4][4];
    #pragma unroll
    for (int i = 0; i < 4; i++)
        #pragma unroll
        for (int j = 0; j < 4; j++) o[i][j] = 0.f;

    for (int kt = 0; kt <= qt; kt++) {
        const int k0 = kt * 64;
        __syncthreads();
        {
            int r  = tid >> 2;
            int c0 = (tid & 3) * 16;
            const float* ks = k + ((size_t)(b * T_ + k0 + r) * H_ + h) * DH_ + c0;
            const float* vs = v + ((size_t)(b * T_ + k0 + r) * H_ + h) * DH_ + c0;
            #pragma unroll
            for (int j = 0; j < 4; j++) {
                float4 t4 = *(const float4*)(ks + j*4);
                Ks[r*65+c0+j*4+0] = t4.x; Ks[r*65+c0+j*4+1] = t4.y;
                Ks[r*65+c0+j*4+2] = t4.z; Ks[r*65+c0+j*4+3] = t4.w;
                float4 u4 = *(const float4*)(vs + j*4);
                Vs[r*65+c0+j*4+0] = u4.x; Vs[r*65+c0+j*4+1] = u4.y;
                Vs[r*65+c0+j*4+2] = u4.z; Vs[r*65+c0+j*4+3] = u4.w;
            }
        }
        __syncthreads();

        float s[4][4];
        #pragma unroll
        for (int i = 0; i < 4; i++)
            #pragma unroll
            for (int j = 0; j < 4; j++) s[i][j] = 0.f;
        for (int d = 0; d < 64; d++) {
            float a[4], bb[4];
            #pragma unroll
            for (int i = 0; i < 4; i++) a[i]  = Qs[(ty*4+i)*65 + d];
            #pragma unroll
            for (int j = 0; j < 4; j++) bb[j] = Ks[(tx*4+j)*65 + d];
            #pragma unroll
            for (int i = 0; i < 4; i++)
                #pragma unroll
                for (int j = 0; j < 4; j++)
                    s[i][j] = fmaf(a[i], bb[j], s[i][j]);
        }
        const bool diag = (kt == qt);
        #pragma unroll
        for (int i = 0; i < 4; i++)
            #pragma unroll
            for (int j = 0; j < 4; j++) {
                float val = s[i][j] * 0.125f;
                if (diag && (tx*4+j) > (ty*4+i)) val = -1e30f;
                Ps[(ty*4+i)*65 + tx*4+j] = val;
            }
        __syncthreads();

        {
            int r  = tid >> 2;
            int c0 = (tid & 3) * 16;
            float mx = -1e30f;
            for (int c = 0; c < 16; c++) mx = fmaxf(mx, Ps[r*65 + c0 + c]);
            mx = fmaxf(mx, __shfl_xor_sync(0xffffffffu, mx, 1));
            mx = fmaxf(mx, __shfl_xor_sync(0xffffffffu, mx, 2));
            float m_old = m_s[r];
            float m_new = fmaxf(m_old, mx);
            float ssum = 0.f;
            for (int c = 0; c < 16; c++) {
                float p = __expf(Ps[r*65 + c0 + c] - m_new);
                Ps[r*65 + c0 + c] = p;
                ssum += p;
            }
            ssum += __shfl_xor_sync(0xffffffffu, ssum, 1);
            ssum += __shfl_xor_sync(0xffffffffu, ssum, 2);
            if ((tid & 3) == 0) {
                float alpha = __expf(m_old - m_new);
                al_s[r] = alpha;
                m_s[r]  = m_new;
                l_s[r]  = l_s[r] * alpha + ssum;
            }
        }
        __syncthreads();

        float al[4];
        #pragma unroll
        for (int i = 0; i < 4; i++) al[i] = al_s[ty*4+i];
        #pragma unroll
        for (int i = 0; i < 4; i++)
            #pragma unroll
            for (int j = 0; j < 4; j++) o[i][j] *= al[i];
        for (int c = 0; c < 64; c++) {
            float p[4], vv[4];
            #pragma unroll
            for (int i = 0; i < 4; i++) p[i]  = Ps[(ty*4+i)*65 + c];
            #pragma unroll
            for (int j = 0; j < 4; j++) vv[j] = Vs[c*65 + tx*4+j];
            #pragma unroll
            for (int i = 0; i < 4; i++)
                #pragma unroll
                for (int j = 0; j < 4; j++)
                    o[i][j] = fmaf(p[i], vv[j], o[i][j]);
        }
    }

    #pragma unroll
    for (int i = 0; i < 4; i++) {
        int r = ty*4 + i;
        float inv = 1.0f / l_s[r];
        float* dst = out + ((size_t)(b * T_ + q0 + r) * H_ + h) * DH_ + tx*4;
        #pragma unroll
        for (int j = 0; j < 4; j++) dst[j] = o[i][j] * inv;
    }
}

// ---------------- layernorm ------------------------------------------------
__global__ void __launch_bounds__(256) ln_kernel(
    const float* __restrict__ in, const float* __restrict__ gg,
    const float* __restrict__ bb, float* __restrict__ out)
{
    __shared__ float red[8];
    const int row = blockIdx.x;
    const int tid = threadIdx.x;
    float4 vx = ((const float4*)(in + (size_t)row * E_))[tid];
    float s = vx.x + vx.y + vx.z + vx.w;
    #pragma unroll
    for (int o = 16; o; o >>= 1) s += __shfl_xor_sync(0xffffffffu, s, o);
    if ((tid & 31) == 0) red[tid >> 5] = s;
    __syncthreads();
    float mean = (red[0]+red[1]+red[2]+red[3]+red[4]+red[5]+red[6]+red[7]) * (1.f/E_);
    __syncthreads();
    float dx = vx.x - mean, dy = vx.y - mean, dz = vx.z - mean, dw = vx.w - mean;
    float s2 = dx*dx + dy*dy + dz*dz + dw*dw;
    #pragma unroll
    for (int o = 16; o; o >>= 1) s2 += __shfl_xor_sync(0xffffffffu, s2, o);
    if ((tid & 31) == 0) red[tid >> 5] = s2;
    __syncthreads();
    float var = (red[0]+red[1]+red[2]+red[3]+red[4]+red[5]+red[6]+red[7]) * (1.f/E_);
    float rstd = rsqrtf(var + 1e-5f);
    float4 g4 = ((const float4*)gg)[tid];
    float4 b4 = ((const float4*)bb)[tid];
    float4 o4 = make_float4(dx*rstd*g4.x + b4.x, dy*rstd*g4.y + b4.y,
                            dz*rstd*g4.z + b4.z, dw*rstd*g4.w + b4.w);
    ((float4*)(out + (size_t)row * E_))[tid] = o4;
}

// ---------------- token+pos embedding --------------------------------------
__global__ void __launch_bounds__(256) embed_kernel(
    const int* __restrict__ idx, const float* __restrict__ tok,
    const float* __restrict__ pos, float* __restrict__ out)
{
    int gid = blockIdx.x * 256 + threadIdx.x;
    int e4 = gid & (E_/4 - 1);
    int bt = gid >> 8;
    int t  = bt & (T_ - 1);
    int token = idx[bt];
    float4 a = ((const float4*)(tok + (size_t)token * E_))[e4];
    float4 p = ((const float4*)(pos + (size_t)t * E_))[e4];
    ((float4*)out)[gid] = make_float4(a.x+p.x, a.y+p.y, a.z+p.z, a.w+p.w);
}

// ---------------- loss -----------------------------------------------------
__global__ void __launch_bounds__(256) loss_tok_kernel(
    const float* __restrict__ logits, const int* __restrict__ targets,
    float* __restrict__ tokloss)
{
    __shared__ float red[8];
    const int row = blockIdx.x;
    const int tid = threadIdx.x;
    const float* lg = logits + (size_t)row * V_;
    float mx = -1e30f;
    for (int i = tid; i < V_; i += 256) mx = fmaxf(mx, lg[i]);
    #pragma unroll
    for (int o = 16; o; o >>= 1) mx = fmaxf(mx, __shfl_xor_sync(0xffffffffu, mx, o));
    if ((tid & 31) == 0) red[tid >> 5] = mx;
    __syncthreads();
    mx = fmaxf(fmaxf(fmaxf(red[0], red[1]), fmaxf(red[2], red[3])),
               fmaxf(fmaxf(red[4], red[5]), fmaxf(red[6], red[7])));
    __syncthreads();
    float s = 0.f;
    for (int i = tid; i < V_; i += 256) s += __expf(lg[i] - mx);
    #pragma unroll
    for (int o = 16; o; o >>= 1) s += __shfl_xor_sync(0xffffffffu, s, o);
    if ((tid & 31) == 0) red[tid >> 5] = s;
    __syncthreads();
    if (tid == 0) {
        float tot = red[0]+red[1]+red[2]+red[3]+red[4]+red[5]+red[6]+red[7];
        tokloss[row] = -(lg[targets[row]] - mx - logf(tot));
    }
}

__global__ void __launch_bounds__(256) loss_reduce_kernel(
    const float* __restrict__ tokloss, float* __restrict__ outp)
{
    __shared__ float red[8];
    const int tid = threadIdx.x;
    float s = 0.f;
    for (int i = tid; i < BT_; i += 256) s += tokloss[i];
    #pragma unroll
    for (int o = 16; o; o >>= 1) s += __shfl_xor_sync(0xffffffffu, s, o);
    if ((tid & 31) == 0) red[tid >> 5] = s;
    __syncthreads();
    if (tid == 0) {
        float tot = red[0]+red[1]+red[2]+red[3]+red[4]+red[5]+red[6]+red[7];
        outp[0] = tot / (float)BT_;
    }
}

// ---------------- host driver ----------------------------------------------
extern "C" void kernel_launch(void* const* d_in, const int* in_sizes, int n_in,
                              void* d_out, int out_size)
{
    const int*   idx  = (const int*)  d_in[0];
    const int*   tgt  = (const int*)  d_in[1];
    const float* tok  = (const float*)d_in[2];
    const float* pos  = (const float*)d_in[3];
    const float* Wq   = (const float*)d_in[4];
    const float* Wk   = (const float*)d_in[5];
    const float* Wv   = (const float*)d_in[6];
    const float* Wo   = (const float*)d_in[7];
    const float* bo   = (const float*)d_in[8];
    const float* ln1g = (const float*)d_in[9];
    const float* ln1b = (const float*)d_in[10];
    const float* W1   = (const float*)d_in[11];
    const float* b1   = (const float*)d_in[12];
    const float* W2   = (const float*)d_in[13];
    const float* b2   = (const float*)d_in[14];
    const float* ln2g = (const float*)d_in[15];
    const float* ln2b = (const float*)d_in[16];
    const float* lnfg = (const float*)d_in[17];
    const float* lnfb = (const float*)d_in[18];
    const float* lmw  = (const float*)d_in[19];
    const float* lmb  = (const float*)d_in[20];

    float *x, *y, *q, *k, *v, *att, *hbuf, *lscratch, *tokloss;
    __nv_bfloat16 *ah, *al, *wh, *wl;
    cudaGetSymbolAddress((void**)&x,        g_x);
    cudaGetSymbolAddress((void**)&y,        g_y);
    cudaGetSymbolAddress((void**)&q,        g_q);
    cudaGetSymbolAddress((void**)&k,        g_k);
    cudaGetSymbolAddress((void**)&v,        g_v);
    cudaGetSymbolAddress((void**)&att,      g_att);
    cudaGetSymbolAddress((void**)&hbuf,     g_h);
    cudaGetSymbolAddress((void**)&lscratch, g_logits);
    cudaGetSymbolAddress((void**)&tokloss,  g_tokloss);
    cudaGetSymbolAddress((void**)&ah,       g_ah);
    cudaGetSymbolAddress((void**)&al,       g_al);
    cudaGetSymbolAddress((void**)&wh,       g_wh);
    cudaGetSymbolAddress((void**)&wl,       g_wl);

    const size_t LOG_N = (size_t)BT_ * V_;
    float* logits_ptr = ((size_t)out_size >= LOG_N) ? (float*)d_out : lscratch;
    float* loss_ptr = nullptr;
    if ((size_t)out_size >= LOG_N + 1) loss_ptr = (float*)d_out + LOG_N;
    else if ((size_t)out_size < LOG_N) loss_ptr = (float*)d_out;

    cudaFuncSetAttribute(attn_kernel, cudaFuncAttributeMaxDynamicSharedMemorySize,
                         ATTN_SMEM_BYTES);
    cudaFuncSetAttribute(gemm_mm<EPI_BIAS|EPI_RES>,
                         cudaFuncAttributeMaxDynamicSharedMemorySize, SMEM_MM);
    cudaFuncSetAttribute(gemm_mm<EPI_BIAS|EPI_GELU>,
                         cudaFuncAttributeMaxDynamicSharedMemorySize, SMEM_MM);
    cudaFuncSetAttribute(gemm_mm<EPI_BIAS>,
                         cudaFuncAttributeMaxDynamicSharedMemorySize, SMEM_MM);

    embed_kernel<<<BT_*(E_/4)/256, 256>>>(idx, tok, pos, x);

    for (int l = 0; l < NL_; l++) {
        gemm_kernel<0><<<dim3(1, MQKV_/128), 256>>>(
            x, Wq + (size_t)l*DH_*DH_, nullptr, nullptr, q, MQKV_, DH_, DH_);
        gemm_kernel<0><<<dim3(1, MQKV_/128), 256>>>(
            x, Wk + (size_t)l*DH_*DH_, nullptr, nullptr, k, MQKV_, DH_, DH_);
        gemm_kernel<0><<<dim3(1, MQKV_/128), 256>>>(
            x, Wv + (size_t)l*DH_*DH_, nullptr, nullptr, v, MQKV_, DH_, DH_);

        attn_kernel<<<dim3(T_/64, B_*H_), 256, ATTN_SMEM_BYTES>>>(q, k, v, att);

        // out-proj: y = att @ Wo^T + bo + x
        cvt_kernel<<<(BT_*E_/4)/256, 256>>>(att, ah, al, BT_*E_/4);
        cvt_kernel<<<(E_*E_/4)/256, 256>>>(Wo + (size_t)l*E_*E_, wh, wl, E_*E_/4);
        gemm_mm<EPI_BIAS|EPI_RES><<<dim3(BT_/128, E_/128), 256, SMEM_MM>>>(
            ah, al, wh, wl, bo + (size_t)l*E_, x, y, BT_, E_, E_);
        ln_kernel<<<BT_, 256>>>(y, ln1g + (size_t)l*E_, ln1b + (size_t)l*E_, x);

        // FF1: h = gelu(x @ W1^T + b1)
        cvt_kernel<<<(BT_*E_/4)/256, 256>>>(x, ah, al, BT_*E_/4);
        cvt_kernel<<<(FF_*E_/4)/256, 256>>>(W1 + (size_t)l*FF_*E_, wh, wl, FF_*E_/4);
        gemm_mm<EPI_BIAS|EPI_GELU><<<dim3(BT_/128, FF_/128), 256, SMEM_MM>>>(
            ah, al, wh, wl, b1 + (size_t)l*FF_, nullptr, hbuf, BT_, FF_, E_);

        // FF2: y = h @ W2^T + b2 + x
        cvt_kernel<<<((size_t)BT_*FF_/4)/256, 256>>>(hbuf, ah, al, BT_*FF_/4);
        cvt_kernel<<<(E_*FF_/4)/256, 256>>>(W2 + (size_t)l*E_*FF_, wh, wl, E_*FF_/4);
        gemm_mm<EPI_BIAS|EPI_RES><<<dim3(BT_/128, E_/128), 256, SMEM_MM>>>(
            ah, al, wh, wl, b2 + (size_t)l*E_, x, y, BT_, E_, FF_);
        ln_kernel<<<BT_, 256>>>(y, ln2g + (size_t)l*E_, ln2b + (size_t)l*E_, x);
    }

    ln_kernel<<<BT_, 256>>>(x, lnfg, lnfb, y);

    // LM head
    cvt_kernel<<<(BT_*E_/4)/256, 256>>>(y, ah, al, BT_*E_/4);
    cvt_kernel<<<((size_t)V_*E_/4)/256, 256>>>(lmw, wh, wl, V_*E_/4);
    gemm_mm<EPI_BIAS><<<dim3(BT_/128, V_/128), 256, SMEM_MM>>>(
        ah, al, wh, wl, lmb, nullptr, logits_ptr, BT_, V_, E_);

    if (loss_ptr) {
        loss_tok_kernel<<<BT_, 256>>>(logits_ptr, tgt, tokloss);
        loss_reduce_kernel<<<1, 256>>>(tokloss, loss_ptr);
    }
}

// round 10
// speedup vs baseline: 1.8451x; 1.5768x over previous
#include <cuda_runtime.h>
#include <cuda_bf16.h>
#include <math.h>
#include <stdint.h>

#define B_  4
#define T_  2048
#define E_  1024
#define H_  16
#define DH_ 64
#define NL_ 4
#define FF_ 4096
#define V_  32000
#define BT_ (B_*T_)        // 8192 tokens
#define MQKV_ (BT_*H_)     // 131072 per-head rows

// ---------------- scratch (static device allocations; no cudaMalloc) -------
__device__ float g_x[BT_*E_];
__device__ float g_y[BT_*E_];
__device__ float g_qkv[(size_t)MQKV_*256];   // packed q|k|v|pad, row stride 256
__device__ float g_att[BT_*E_];
__device__ float g_h[(size_t)BT_*FF_];
__device__ float g_logits[(size_t)BT_*V_];
__device__ float g_tokloss[BT_];
// bf16 hi/lo split buffers
__device__ __nv_bfloat16 g_ah[(size_t)BT_*FF_];
__device__ __nv_bfloat16 g_al[(size_t)BT_*FF_];
__device__ __nv_bfloat16 g_wh[(size_t)V_*E_];
__device__ __nv_bfloat16 g_wl[(size_t)V_*E_];
__device__ __nv_bfloat16 g_wqh[256*64];
__device__ __nv_bfloat16 g_wql[256*64];

// ======================= low-level helpers =================================
__device__ __forceinline__ uint32_t smem_u32(const void* p) {
    uint32_t a;
    asm("{ .reg .u64 t; cvta.to.shared.u64 t, %1; cvt.u32.u64 %0, t; }"
        : "=r"(a) : "l"(p));
    return a;
}
__device__ __forceinline__ void cp16(uint32_t dst, const void* src) {
    asm volatile("cp.async.cg.shared.global [%0], [%1], 16;\n"
                 :: "r"(dst), "l"(src));
}
__device__ __forceinline__ void cp_commit() {
    asm volatile("cp.async.commit_group;" ::: "memory");
}
__device__ __forceinline__ void cp_wait1() {
    asm volatile("cp.async.wait_group 1;" ::: "memory");
}
__device__ __forceinline__ void cp_wait0() {
    asm volatile("cp.async.wait_group 0;" ::: "memory");
}
#define LDSM4(r0,r1,r2,r3,addr) \
    asm volatile("ldmatrix.sync.aligned.m8n8.x4.shared.b16 {%0,%1,%2,%3}, [%4];" \
        : "=r"(r0),"=r"(r1),"=r"(r2),"=r"(r3) : "r"(addr))
#define LDSM2(r0,r1,addr) \
    asm volatile("ldmatrix.sync.aligned.m8n8.x2.shared.b16 {%0,%1}, [%2];" \
        : "=r"(r0),"=r"(r1) : "r"(addr))
#define MMA16816(c,a,b) \
    asm volatile("mma.sync.aligned.m16n8k16.row.col.f32.bf16.bf16.f32 " \
        "{%0,%1,%2,%3}, {%4,%5,%6,%7}, {%8,%9}, {%0,%1,%2,%3};" \
        : "+f"((c)[0]),"+f"((c)[1]),"+f"((c)[2]),"+f"((c)[3]) \
        : "r"((a)[0]),"r"((a)[1]),"r"((a)[2]),"r"((a)[3]), \
          "r"((b)[0]),"r"((b)[1]))

// ======================= bf16 hi/lo HMMA GEMM ==============================
// C[M,N] = (Ah+Al)[M,K] @ (Bh+Bl)[N,K]^T, fp32 out, 3-pass split precision.
// Block 128x128, K-chunk 32, 8 warps (2M x 4N, warp tile 64x32), 2-stage
// cp.async pipeline, 80B-padded smem rows (conflict-free ldmatrix).
// Passes swept separately over all fragments (RAW reuse distance = 16 MMAs).
#define EPI_BIAS 1
#define EPI_RES  2
#define EPI_GELU 4

#define PAD_ROW 80                    // bytes per smem row: 64B data + 16B pad
#define TILE_BYTES (128*PAD_ROW)      // 10240
#define S_AH 0
#define S_AL (TILE_BYTES)
#define S_BH (2*TILE_BYTES)
#define S_BL (3*TILE_BYTES)
#define STAGE_MM (4*TILE_BYTES)       // 40960
#define SMEM_MM  (2*STAGE_MM)         // 81920

__device__ __forceinline__ void mm_load(
    uint32_t st, const __nv_bfloat16* __restrict__ Ah,
    const __nv_bfloat16* __restrict__ Al,
    const __nv_bfloat16* __restrict__ Bh,
    const __nv_bfloat16* __restrict__ Bl,
    int m0, int n0, int K, int k0, int tid)
{
    #pragma unroll
    for (int j = 0; j < 2; j++) {
        int ch  = tid + j * 256;          // 0..511
        int row = ch >> 2;
        int c16 = ch & 3;
        uint32_t so = row * PAD_ROW + c16 * 16;
        size_t goA = (size_t)(m0 + row) * K + k0 + c16 * 8;
        size_t goB = (size_t)(n0 + row) * K + k0 + c16 * 8;
        cp16(st + S_AH + so, Ah + goA);
        cp16(st + S_AL + so, Al + goA);
        cp16(st + S_BH + so, Bh + goB);
        cp16(st + S_BL + so, Bl + goB);
    }
}

template<int EPI>
__global__ void __launch_bounds__(256) gemm_mm(
    const __nv_bfloat16* __restrict__ Ah, const __nv_bfloat16* __restrict__ Al,
    const __nv_bfloat16* __restrict__ Bh, const __nv_bfloat16* __restrict__ Bl,
    const float* __restrict__ bias, const float* __restrict__ res,
    float* __restrict__ C, int M, int N, int K)
{
    extern __shared__ char smraw[];
    const uint32_t sb = smem_u32(smraw);
    const int tid  = threadIdx.x;
    const int lane = tid & 31;
    const int wid  = tid >> 5;
    const int wm = (wid & 1) * 64;        // warp M offset in block
    const int wn = (wid >> 1) * 32;       // warp N offset in block
    const int m0 = blockIdx.x * 128;
    const int n0 = blockIdx.y * 128;
    const int NC = K >> 5;                // chunks of 32

    float c[4][4][4];
    #pragma unroll
    for (int i = 0; i < 4; i++)
        #pragma unroll
        for (int j = 0; j < 4; j++)
            #pragma unroll
            for (int r = 0; r < 4; r++) c[i][j][r] = 0.f;

    // ldmatrix per-lane address components (constant across chunks)
    const int a_row = wm + (lane & 15);
    const int a_kof = (lane >> 4) * 8;
    const int b_row = wn + (lane & 7);
    const int b_kof = ((lane >> 3) & 1) * 8;

    mm_load(sb, Ah, Al, Bh, Bl, m0, n0, K, 0, tid);
    cp_commit();

    for (int ck = 0; ck < NC; ck++) {
        if (ck + 1 < NC) {
            mm_load(sb + ((ck + 1) & 1) * STAGE_MM, Ah, Al, Bh, Bl,
                    m0, n0, K, (ck + 1) << 5, tid);
            cp_commit();
            cp_wait1();
        } else {
            cp_wait0();
        }
        __syncthreads();

        const uint32_t st = sb + (ck & 1) * STAGE_MM;
        #pragma unroll
        for (int ks = 0; ks < 2; ks++) {
            const int k0 = ks * 16;
            uint32_t ah[4][4], al[4][4], bh[4][2], bl[4][2];
            #pragma unroll
            for (int mi = 0; mi < 4; mi++) {
                uint32_t ad = st + (a_row + mi * 16) * PAD_ROW + (k0 + a_kof) * 2;
                LDSM4(ah[mi][0], ah[mi][1], ah[mi][2], ah[mi][3], ad + S_AH);
                LDSM4(al[mi][0], al[mi][1], al[mi][2], al[mi][3], ad + S_AL);
            }
            #pragma unroll
            for (int ni = 0; ni < 4; ni++) {
                uint32_t bd = st + (b_row + ni * 8) * PAD_ROW + (k0 + b_kof) * 2;
                LDSM2(bh[ni][0], bh[ni][1], bd + S_BH);
                LDSM2(bl[ni][0], bl[ni][1], bd + S_BL);
            }
            // pass 1: Ah*Bh — all 16 fragments (no same-acc back-to-back RAW)
            #pragma unroll
            for (int mi = 0; mi < 4; mi++)
                #pragma unroll
                for (int ni = 0; ni < 4; ni++)
                    MMA16816(c[mi][ni], ah[mi], bh[ni]);
            // pass 2: Ah*Bl
            #pragma unroll
            for (int mi = 0; mi < 4; mi++)
                #pragma unroll
                for (int ni = 0; ni < 4; ni++)
                    MMA16816(c[mi][ni], ah[mi], bl[ni]);
            // pass 3: Al*Bh
            #pragma unroll
            for (int mi = 0; mi < 4; mi++)
                #pragma unroll
                for (int ni = 0; ni < 4; ni++)
                    MMA16816(c[mi][ni], al[mi], bh[ni]);
        }
        __syncthreads();
    }

    // epilogue: c frag rows = lane>>2 (+8), cols = 2*(lane&3) (+1)
    #pragma unroll
    for (int mi = 0; mi < 4; mi++) {
        const int mr = m0 + wm + mi * 16 + (lane >> 2);
        #pragma unroll
        for (int half = 0; half < 2; half++) {
            const int m = mr + half * 8;
            #pragma unroll
            for (int ni = 0; ni < 4; ni++) {
                const int n = n0 + wn + ni * 8 + 2 * (lane & 3);
                float v0 = c[mi][ni][half * 2 + 0];
                float v1 = c[mi][ni][half * 2 + 1];
                if (EPI & EPI_BIAS) { v0 += bias[n]; v1 += bias[n + 1]; }
                if (EPI & EPI_RES) {
                    float2 r2 = *(const float2*)(res + (size_t)m * N + n);
                    v0 += r2.x; v1 += r2.y;
                }
                if (EPI & EPI_GELU) {
                    v0 = 0.5f * v0 * (1.f + erff(v0 * 0.70710678118654752f));
                    v1 = 0.5f * v1 * (1.f + erff(v1 * 0.70710678118654752f));
                }
                *(float2*)(C + (size_t)m * N + n) = make_float2(v0, v1);
            }
        }
    }
}

// ---------------- fp32 -> bf16 hi/lo conversion ----------------------------
__global__ void __launch_bounds__(256) cvt_kernel(
    const float* __restrict__ in, __nv_bfloat16* __restrict__ hi,
    __nv_bfloat16* __restrict__ lo, int n4)
{
    int i = blockIdx.x * 256 + threadIdx.x;
    if (i >= n4) return;
    float4 x = ((const float4*)in)[i];
    __nv_bfloat16 h0 = __float2bfloat16(x.x);
    __nv_bfloat16 h1 = __float2bfloat16(x.y);
    __nv_bfloat16 h2 = __float2bfloat16(x.z);
    __nv_bfloat16 h3 = __float2bfloat16(x.w);
    __nv_bfloat16 l0 = __float2bfloat16(x.x - __bfloat162float(h0));
    __nv_bfloat16 l1 = __float2bfloat16(x.y - __bfloat162float(h1));
    __nv_bfloat16 l2 = __float2bfloat16(x.z - __bfloat162float(h2));
    __nv_bfloat16 l3 = __float2bfloat16(x.w - __bfloat162float(h3));
    ((__nv_bfloat162*)hi)[2*i]   = __nv_bfloat162(h0, h1);
    ((__nv_bfloat162*)hi)[2*i+1] = __nv_bfloat162(h2, h3);
    ((__nv_bfloat162*)lo)[2*i]   = __nv_bfloat162(l0, l1);
    ((__nv_bfloat162*)lo)[2*i+1] = __nv_bfloat162(l2, l3);
}

// ---------------- pack Wq|Wk|Wv -> padded [256 x 64] bf16 hi/lo ------------
__global__ void __launch_bounds__(256) pack_qkv_kernel(
    const float* __restrict__ Wq, const float* __restrict__ Wk,
    const float* __restrict__ Wv,
    __nv_bfloat16* __restrict__ wh, __nv_bfloat16* __restrict__ wl)
{
    int i = blockIdx.x * 256 + threadIdx.x;   // 0..16383
    int row = i >> 6, col = i & 63;
    float v = 0.f;
    if (row < 64)       v = Wq[row * 64 + col];
    else if (row < 128) v = Wk[(row - 64) * 64 + col];
    else if (row < 192) v = Wv[(row - 128) * 64 + col];
    __nv_bfloat16 h = __float2bfloat16(v);
    wh[i] = h;
    wl[i] = __float2bfloat16(v - __bfloat162float(h));
}

// ---------------- flash attention (causal, online softmax, fp32) -----------
// reads packed qkv rows of stride 256: [q(64) | k(64) | v(64) | pad(64)]
#define ATTN_SMEM_FLOATS (4*64*65 + 3*64)
#define ATTN_SMEM_BYTES  (ATTN_SMEM_FLOATS * 4)

__global__ void __launch_bounds__(256) attn_kernel(
    const float* __restrict__ qkv, float* __restrict__ out)
{
    extern __shared__ float sm[];
    float* Qs  = sm;
    float* Ks  = sm + 64*65;
    float* Vs  = sm + 2*64*65;
    float* Ps  = sm + 3*64*65;
    float* m_s = sm + 4*64*65;
    float* l_s = m_s + 64;
    float* al_s= l_s + 64;

    const int qt = blockIdx.x;
    const int bh = blockIdx.y;
    const int b  = bh / H_, h = bh % H_;
    const int q0 = qt * 64;
    const int tid = threadIdx.x;
    const int tx = tid & 15, ty = tid >> 4;

    {
        int r  = tid >> 2;
        int c0 = (tid & 3) * 16;
        const float* src = qkv + ((size_t)(b * T_ + q0 + r) * H_ + h) * 256 + c0;
        #pragma unroll
        for (int j = 0; j < 4; j++) {
            float4 t4 = *(const float4*)(src + j*4);
            Qs[r*65 + c0 + j*4 + 0] = t4.x;
            Qs[r*65 + c0 + j*4 + 1] = t4.y;
            Qs[r*65 + c0 + j*4 + 2] = t4.z;
            Qs[r*65 + c0 + j*4 + 3] = t4.w;
        }
    }
    if (tid < 64) { m_s[tid] = -1e30f; l_s[tid] = 0.f; }

    float o[4][4];
    #pragma unroll
    for (int i = 0; i < 4; i++)
        #pragma unroll
        for (int j = 0; j < 4; j++) o[i][j] = 0.f;

    for (int kt = 0; kt <= qt; kt++) {
        const int k0 = kt * 64;
        __syncthreads();
        {
            int r  = tid >> 2;
            int c0 = (tid & 3) * 16;
            const float* base = qkv + ((size_t)(b * T_ + k0 + r) * H_ + h) * 256;
            #pragma unroll
            for (int j = 0; j < 4; j++) {
                float4 t4 = *(const float4*)(base + 64 + c0 + j*4);
                Ks[r*65+c0+j*4+0] = t4.x; Ks[r*65+c0+j*4+1] = t4.y;
                Ks[r*65+c0+j*4+2] = t4.z; Ks[r*65+c0+j*4+3] = t4.w;
                float4 u4 = *(const float4*)(base + 128 + c0 + j*4);
                Vs[r*65+c0+j*4+0] = u4.x; Vs[r*65+c0+j*4+1] = u4.y;
                Vs[r*65+c0+j*4+2] = u4.z; Vs[r*65+c0+j*4+3] = u4.w;
            }
        }
        __syncthreads();

        float s[4][4];
        #pragma unroll
        for (int i = 0; i < 4; i++)
            #pragma unroll
            for (int j = 0; j < 4; j++) s[i][j] = 0.f;
        for (int d = 0; d < 64; d++) {
            float a[4], bb[4];
            #pragma unroll
            for (int i = 0; i < 4; i++) a[i]  = Qs[(ty*4+i)*65 + d];
            #pragma unroll
            for (int j = 0; j < 4; j++) bb[j] = Ks[(tx*4+j)*65 + d];
            #pragma unroll
            for (int i = 0; i < 4; i++)
                #pragma unroll
                for (int j = 0; j < 4; j++)
                    s[i][j] = fmaf(a[i], bb[j], s[i][j]);
        }
        const bool diag = (kt == qt);
        #pragma unroll
        for (int i = 0; i < 4; i++)
            #pragma unroll
            for (int j = 0; j < 4; j++) {
                float val = s[i][j] * 0.125f;
                if (diag && (tx*4+j) > (ty*4+i)) val = -1e30f;
                Ps[(ty*4+i)*65 + tx*4+j] = val;
            }
        __syncthreads();

        {
            int r  = tid >> 2;
            int c0 = (tid & 3) * 16;
            float mx = -1e30f;
            for (int c = 0; c < 16; c++) mx = fmaxf(mx, Ps[r*65 + c0 + c]);
            mx = fmaxf(mx, __shfl_xor_sync(0xffffffffu, mx, 1));
            mx = fmaxf(mx, __shfl_xor_sync(0xffffffffu, mx, 2));
            float m_old = m_s[r];
            float m_new = fmaxf(m_old, mx);
            float ssum = 0.f;
            for (int c = 0; c < 16; c++) {
                float p = __expf(Ps[r*65 + c0 + c] - m_new);
                Ps[r*65 + c0 + c] = p;
                ssum += p;
            }
            ssum += __shfl_xor_sync(0xffffffffu, ssum, 1);
            ssum += __shfl_xor_sync(0xffffffffu, ssum, 2);
            if ((tid & 3) == 0) {
                float alpha = __expf(m_old - m_new);
                al_s[r] = alpha;
                m_s[r]  = m_new;
                l_s[r]  = l_s[r] * alpha + ssum;
            }
        }
        __syncthreads();

        float al[4];
        #pragma unroll
        for (int i = 0; i < 4; i++) al[i] = al_s[ty*4+i];
        #pragma unroll
        for (int i = 0; i < 4; i++)
            #pragma unroll
            for (int j = 0; j < 4; j++) o[i][j] *= al[i];
        for (int c = 0; c < 64; c++) {
            float p[4], vv[4];
            #pragma unroll
            for (int i = 0; i < 4; i++) p[i]  = Ps[(ty*4+i)*65 + c];
            #pragma unroll
            for (int j = 0; j < 4; j++) vv[j] = Vs[c*65 + tx*4+j];
            #pragma unroll
            for (int i = 0; i < 4; i++)
                #pragma unroll
                for (int j = 0; j < 4; j++)
                    o[i][j] = fmaf(p[i], vv[j], o[i][j]);
        }
    }

    #pragma unroll
    for (int i = 0; i < 4; i++) {
        int r = ty*4 + i;
        float inv = 1.0f / l_s[r];
        float* dst = out + ((size_t)(b * T_ + q0 + r) * H_ + h) * DH_ + tx*4;
        #pragma unroll
        for (int j = 0; j < 4; j++) dst[j] = o[i][j] * inv;
    }
}

// ---------------- layernorm ------------------------------------------------
__global__ void __launch_bounds__(256) ln_kernel(
    const float* __restrict__ in, const float* __restrict__ gg,
    const float* __restrict__ bb, float* __restrict__ out)
{
    __shared__ float red[8];
    const int row = blockIdx.x;
    const int tid = threadIdx.x;
    float4 vx = ((const float4*)(in + (size_t)row * E_))[tid];
    float s = vx.x + vx.y + vx.z + vx.w;
    #pragma unroll
    for (int o = 16; o; o >>= 1) s += __shfl_xor_sync(0xffffffffu, s, o);
    if ((tid & 31) == 0) red[tid >> 5] = s;
    __syncthreads();
    float mean = (red[0]+red[1]+red[2]+red[3]+red[4]+red[5]+red[6]+red[7]) * (1.f/E_);
    __syncthreads();
    float dx = vx.x - mean, dy = vx.y - mean, dz = vx.z - mean, dw = vx.w - mean;
    float s2 = dx*dx + dy*dy + dz*dz + dw*dw;
    #pragma unroll
    for (int o = 16; o; o >>= 1) s2 += __shfl_xor_sync(0xffffffffu, s2, o);
    if ((tid & 31) == 0) red[tid >> 5] = s2;
    __syncthreads();
    float var = (red[0]+red[1]+red[2]+red[3]+red[4]+red[5]+red[6]+red[7]) * (1.f/E_);
    float rstd = rsqrtf(var + 1e-5f);
    float4 g4 = ((const float4*)gg)[tid];
    float4 b4 = ((const float4*)bb)[tid];
    float4 o4 = make_float4(dx*rstd*g4.x + b4.x, dy*rstd*g4.y + b4.y,
                            dz*rstd*g4.z + b4.z, dw*rstd*g4.w + b4.w);
    ((float4*)(out + (size_t)row * E_))[tid] = o4;
}

// ---------------- token+pos embedding --------------------------------------
__global__ void __launch_bounds__(256) embed_kernel(
    const int* __restrict__ idx, const float* __restrict__ tok,
    const float* __restrict__ pos, float* __restrict__ out)
{
    int gid = blockIdx.x * 256 + threadIdx.x;
    int e4 = gid & (E_/4 - 1);
    int bt = gid >> 8;
    int t  = bt & (T_ - 1);
    int token = idx[bt];
    float4 a = ((const float4*)(tok + (size_t)token * E_))[e4];
    float4 p = ((const float4*)(pos + (size_t)t * E_))[e4];
    ((float4*)out)[gid] = make_float4(a.x+p.x, a.y+p.y, a.z+p.z, a.w+p.w);
}

// ---------------- loss -----------------------------------------------------
__global__ void __launch_bounds__(256) loss_tok_kernel(
    const float* __restrict__ logits, const int* __restrict__ targets,
    float* __restrict__ tokloss)
{
    __shared__ float red[8];
    const int row = blockIdx.x;
    const int tid = threadIdx.x;
    const float* lg = logits + (size_t)row * V_;
    float mx = -1e30f;
    for (int i = tid; i < V_; i += 256) mx = fmaxf(mx, lg[i]);
    #pragma unroll
    for (int o = 16; o; o >>= 1) mx = fmaxf(mx, __shfl_xor_sync(0xffffffffu, mx, o));
    if ((tid & 31) == 0) red[tid >> 5] = mx;
    __syncthreads();
    mx = fmaxf(fmaxf(fmaxf(red[0], red[1]), fmaxf(red[2], red[3])),
               fmaxf(fmaxf(red[4], red[5]), fmaxf(red[6], red[7])));
    __syncthreads();
    float s = 0.f;
    for (int i = tid; i < V_; i += 256) s += __expf(lg[i] - mx);
    #pragma unroll
    for (int o = 16; o; o >>= 1) s += __shfl_xor_sync(0xffffffffu, s, o);
    if ((tid & 31) == 0) red[tid >> 5] = s;
    __syncthreads();
    if (tid == 0) {
        float tot = red[0]+red[1]+red[2]+red[3]+red[4]+red[5]+red[6]+red[7];
        tokloss[row] = -(lg[targets[row]] - mx - logf(tot));
    }
}

__global__ void __launch_bounds__(256) loss_reduce_kernel(
    const float* __restrict__ tokloss, float* __restrict__ outp)
{
    __shared__ float red[8];
    const int tid = threadIdx.x;
    float s = 0.f;
    for (int i = tid; i < BT_; i += 256) s += tokloss[i];
    #pragma unroll
    for (int o = 16; o; o >>= 1) s += __shfl_xor_sync(0xffffffffu, s, o);
    if ((tid & 31) == 0) red[tid >> 5] = s;
    __syncthreads();
    if (tid == 0) {
        float tot = red[0]+red[1]+red[2]+red[3]+red[4]+red[5]+red[6]+red[7];
        outp[0] = tot / (float)BT_;
    }
}

// ---------------- host driver ----------------------------------------------
extern "C" void kernel_launch(void* const* d_in, const int* in_sizes, int n_in,
                              void* d_out, int out_size)
{
    const int*   idx  = (const int*)  d_in[0];
    const int*   tgt  = (const int*)  d_in[1];
    const float* tok  = (const float*)d_in[2];
    const float* pos  = (const float*)d_in[3];
    const float* Wq   = (const float*)d_in[4];
    const float* Wk   = (const float*)d_in[5];
    const float* Wv   = (const float*)d_in[6];
    const float* Wo   = (const float*)d_in[7];
    const float* bo   = (const float*)d_in[8];
    const float* ln1g = (const float*)d_in[9];
    const float* ln1b = (const float*)d_in[10];
    const float* W1   = (const float*)d_in[11];
    const float* b1   = (const float*)d_in[12];
    const float* W2   = (const float*)d_in[13];
    const float* b2   = (const float*)d_in[14];
    const float* ln2g = (const float*)d_in[15];
    const float* ln2b = (const float*)d_in[16];
    const float* lnfg = (const float*)d_in[17];
    const float* lnfb = (const float*)d_in[18];
    const float* lmw  = (const float*)d_in[19];
    const float* lmb  = (const float*)d_in[20];

    float *x, *y, *qkv, *att, *hbuf, *lscratch, *tokloss;
    __nv_bfloat16 *ah, *al, *wh, *wl, *wqh, *wql;
    cudaGetSymbolAddress((void**)&x,        g_x);
    cudaGetSymbolAddress((void**)&y,        g_y);
    cudaGetSymbolAddress((void**)&qkv,      g_qkv);
    cudaGetSymbolAddress((void**)&att,      g_att);
    cudaGetSymbolAddress((void**)&hbuf,     g_h);
    cudaGetSymbolAddress((void**)&lscratch, g_logits);
    cudaGetSymbolAddress((void**)&tokloss,  g_tokloss);
    cudaGetSymbolAddress((void**)&ah,       g_ah);
    cudaGetSymbolAddress((void**)&al,       g_al);
    cudaGetSymbolAddress((void**)&wh,       g_wh);
    cudaGetSymbolAddress((void**)&wl,       g_wl);
    cudaGetSymbolAddress((void**)&wqh,      g_wqh);
    cudaGetSymbolAddress((void**)&wql,      g_wql);

    const size_t LOG_N = (size_t)BT_ * V_;
    float* logits_ptr = ((size_t)out_size >= LOG_N) ? (float*)d_out : lscratch;
    float* loss_ptr = nullptr;
    if ((size_t)out_size >= LOG_N + 1) loss_ptr = (float*)d_out + LOG_N;
    else if ((size_t)out_size < LOG_N) loss_ptr = (float*)d_out;

    cudaFuncSetAttribute(attn_kernel, cudaFuncAttributeMaxDynamicSharedMemorySize,
                         ATTN_SMEM_BYTES);
    cudaFuncSetAttribute(gemm_mm<0>,
                         cudaFuncAttributeMaxDynamicSharedMemorySize, SMEM_MM);
    cudaFuncSetAttribute(gemm_mm<EPI_BIAS|EPI_RES>,
                         cudaFuncAttributeMaxDynamicSharedMemorySize, SMEM_MM);
    cudaFuncSetAttribute(gemm_mm<EPI_BIAS|EPI_GELU>,
                         cudaFuncAttributeMaxDynamicSharedMemorySize, SMEM_MM);
    cudaFuncSetAttribute(gemm_mm<EPI_BIAS>,
                         cudaFuncAttributeMaxDynamicSharedMemorySize, SMEM_MM);

    embed_kernel<<<BT_*(E_/4)/256, 256>>>(idx, tok, pos, x);

    for (int l = 0; l < NL_; l++) {
        // QKV via HMMA: qkv[131072, 256] = x[131072, 64] @ Wqkv[256, 64]^T
        cvt_kernel<<<(BT_*E_/4)/256, 256>>>(x, ah, al, BT_*E_/4);
        pack_qkv_kernel<<<64, 256>>>(Wq + (size_t)l*DH_*DH_,
                                     Wk + (size_t)l*DH_*DH_,
                                     Wv + (size_t)l*DH_*DH_, wqh, wql);
        gemm_mm<0><<<dim3(MQKV_/128, 2), 256, SMEM_MM>>>(
            ah, al, wqh, wql, nullptr, nullptr, qkv, MQKV_, 256, 64);

        attn_kernel<<<dim3(T_/64, B_*H_), 256, ATTN_SMEM_BYTES>>>(qkv, att);

        // out-proj: y = att @ Wo^T + bo + x
        cvt_kernel<<<(BT_*E_/4)/256, 256>>>(att, ah, al, BT_*E_/4);
        cvt_kernel<<<(E_*E_/4)/256, 256>>>(Wo + (size_t)l*E_*E_, wh, wl, E_*E_/4);
        gemm_mm<EPI_BIAS|EPI_RES><<<dim3(BT_/128, E_/128), 256, SMEM_MM>>>(
            ah, al, wh, wl, bo + (size_t)l*E_, x, y, BT_, E_, E_);
        ln_kernel<<<BT_, 256>>>(y, ln1g + (size_t)l*E_, ln1b + (size_t)l*E_, x);

        // FF1: h = gelu(x @ W1^T + b1)
        cvt_kernel<<<(BT_*E_/4)/256, 256>>>(x, ah, al, BT_*E_/4);
        cvt_kernel<<<(FF_*E_/4)/256, 256>>>(W1 + (size_t)l*FF_*E_, wh, wl, FF_*E_/4);
        gemm_mm<EPI_BIAS|EPI_GELU><<<dim3(BT_/128, FF_/128), 256, SMEM_MM>>>(
            ah, al, wh, wl, b1 + (size_t)l*FF_, nullptr, hbuf, BT_, FF_, E_);

        // FF2: y = h @ W2^T + b2 + x
        cvt_kernel<<<((size_t)BT_*FF_/4)/256, 256>>>(hbuf, ah, al, BT_*FF_/4);
        cvt_kernel<<<(E_*FF_/4)/256, 256>>>(W2 + (size_t)l*E_*FF_, wh, wl, E_*FF_/4);
        gemm_mm<EPI_BIAS|EPI_RES><<<dim3(BT_/128, E_/128), 256, SMEM_MM>>>(
            ah, al, wh, wl, b2 + (size_t)l*E_, x, y, BT_, E_, FF_);
        ln_kernel<<<BT_, 256>>>(y, ln2g + (size_t)l*E_, ln2b + (size_t)l*E_, x);
    }

    ln_kernel<<<BT_, 256>>>(x, lnfg, lnfb, y);

    // LM head
    cvt_kernel<<<(BT_*E_/4)/256, 256>>>(y, ah, al, BT_*E_/4);
    cvt_kernel<<<((size_t)V_*E_/4)/256, 256>>>(lmw, wh, wl, V_*E_/4);
    gemm_mm<EPI_BIAS><<<dim3(BT_/128, V_/128), 256, SMEM_MM>>>(
        ah, al, wh, wl, lmb, nullptr, logits_ptr, BT_, V_, E_);

    if (loss_ptr) {
        loss_tok_kernel<<<BT_, 256>>>(logits_ptr, tgt, tokloss);
        loss_reduce_kernel<<<1, 256>>>(tokloss, loss_ptr);
    }
}